// round 1
// baseline (speedup 1.0000x reference)
#include <cuda_runtime.h>
#include <math.h>

#define B_SZ      4096
#define DIM       128
#define HIST      50
#define TOPN      4
#define PROTO     1024
#define ITEM_NUM  100000
#define KTOT      1152   // 384 text + 768 visual

// ---------------- scratch (static device globals; no allocation) ----------------
__device__ float g_Wc[KTOT * DIM];      // transposed combined [k][d] weight (Wt|Wv)
__device__ float g_W1T[256 * DIM];      // W1 transposed [k][d]
__device__ float g_cbias[DIM];          // (bt @ Wt.T + bv @ Wv.T)
__device__ float g_feat[B_SZ * 256];    // [h_u_hat | e_i_hat]
__device__ float g_f1[B_SZ * DIM];      // relu(feat @ W1.T + b1)
__device__ float g_f2[B_SZ * 64];       // relu(bn(f1) @ W2.T + b2)
__device__ float g_p1s[64 * 128];       // stage-1 partial sums (f1)
__device__ float g_p1q[64 * 128];
__device__ float g_p2s[64 * 64];        // stage-1 partials (f2)
__device__ float g_p2q[64 * 64];
__device__ float g_effW2T[128 * 64];    // W2 with BN1 folded, [k][d]
__device__ float g_effb2[64];
__device__ float g_effWp[64];           // Wp with BN2 folded
__device__ float g_effbp;

// ---------------- prep: transposes ----------------
__global__ void k_transpose(const float* __restrict__ Wt,
                            const float* __restrict__ Wv,
                            const float* __restrict__ W1) {
    int i = blockIdx.x * blockDim.x + threadIdx.x;
    const int T1 = KTOT * DIM;          // 147456
    const int T2 = 256 * DIM;           // 32768
    if (i < T1) {
        int k = i >> 7, d = i & 127;
        g_Wc[i] = (k < 384) ? Wt[d * 384 + k] : Wv[d * 768 + (k - 384)];
    } else if (i < T1 + T2) {
        int j = i - T1;
        int k = j >> 7, d = j & 127;
        g_W1T[j] = W1[d * 256 + k];
    }
}

// ---------------- prep: constant bias projection ----------------
__global__ void k_cbias(const float* __restrict__ Wt, const float* __restrict__ Wv,
                        const float* __restrict__ bt, const float* __restrict__ bv) {
    int d = blockIdx.x;
    int tid = threadIdx.x;
    float s = 0.f;
    for (int k = tid; k < KTOT; k += 128) {
        float w = (k < 384) ? Wt[d * 384 + k] : Wv[d * 768 + (k - 384)];
        float b = (k < 384) ? bt[k] : bv[k - 384];
        s = fmaf(w, b, s);
    }
    __shared__ float red[128];
    red[tid] = s;
    __syncthreads();
    for (int o = 64; o > 0; o >>= 1) {
        if (tid < o) red[tid] += red[tid + o];
        __syncthreads();
    }
    if (tid == 0) g_cbias[d] = red[0];
}

// ---------------- h_u + prompt gathers (8 rows / block, 128 threads) ----------------
__global__ void k_hu(const int* __restrict__ nodes_u, const int* __restrict__ nodes_d,
                     const int* __restrict__ inter_items, const int* __restrict__ top_n,
                     const float* __restrict__ proto,
                     const float* __restrict__ user_prompt,
                     const float* __restrict__ domain_prompt,
                     float* __restrict__ out_pu, float* __restrict__ out_hu,
                     float* __restrict__ out_pd) {
    __shared__ unsigned mask[8][32];
    __shared__ float fmask[8][PROTO];
    __shared__ float s_invc[8];

    int tid = threadIdx.x;
    int warp = tid >> 5, lane = tid & 31;
    int row0 = blockIdx.x * 8;

    for (int i = tid; i < 8 * 32; i += 128) ((unsigned*)mask)[i] = 0u;
    __syncthreads();

    // 8 rows * 50 items * 2 views * 4 = 3200 index insertions
    for (int t = tid; t < 3200; t += 128) {
        int r = t / 400;
        int e = t - r * 400;
        int slot = e >> 3;
        int w = e & 7;
        int half = w >> 2;
        int j = w & 3;
        int item = inter_items[(row0 + r) * HIST + slot];
        int p = top_n[(item + half * ITEM_NUM) * TOPN + j];
        atomicOr(&mask[r][p >> 5], 1u << (p & 31));
    }
    __syncthreads();

    // expand to float mask in smem
    for (int i = tid; i < 8 * PROTO; i += 128) {
        int r = i >> 10, p = i & (PROTO - 1);
        fmask[r][p] = (float)((mask[r][p >> 5] >> (p & 31)) & 1u);
    }
    if (tid < 8) {
        int c = 0;
        #pragma unroll
        for (int w = 0; w < 32; ++w) c += __popc(mask[tid][w]);
        s_invc[tid] = 1.0f / (float)c;
    }
    __syncthreads();

    // warp handles 2 rows, lane handles 4 dims
    int r0 = 2 * warp, r1 = r0 + 1;
    float a0x = 0.f, a0y = 0.f, a0z = 0.f, a0w = 0.f;
    float a1x = 0.f, a1y = 0.f, a1z = 0.f, a1w = 0.f;

    #pragma unroll 4
    for (int p = 0; p < PROTO; ++p) {
        float4 v = *(const float4*)&proto[p * DIM + 4 * lane];
        float m0 = fmask[r0][p];
        float m1 = fmask[r1][p];
        a0x = fmaf(m0, v.x, a0x); a0y = fmaf(m0, v.y, a0y);
        a0z = fmaf(m0, v.z, a0z); a0w = fmaf(m0, v.w, a0w);
        a1x = fmaf(m1, v.x, a1x); a1y = fmaf(m1, v.y, a1y);
        a1z = fmaf(m1, v.z, a1z); a1w = fmaf(m1, v.w, a1w);
    }

    #pragma unroll
    for (int rr = 0; rr < 2; ++rr) {
        int r = r0 + rr;
        int row = row0 + r;
        float ic = s_invc[r];
        float4 hu;
        if (rr == 0) { hu.x = a0x * ic; hu.y = a0y * ic; hu.z = a0z * ic; hu.w = a0w * ic; }
        else         { hu.x = a1x * ic; hu.y = a1y * ic; hu.z = a1z * ic; hu.w = a1w * ic; }
        int dn = nodes_d[row];
        int un = nodes_u[row];
        float4 pd = *(const float4*)&domain_prompt[dn * DIM + 4 * lane];
        float4 pu = *(const float4*)&user_prompt[(long)un * DIM + 4 * lane];
        *(float4*)&out_hu[(long)row * DIM + 4 * lane] = hu;
        *(float4*)&out_pd[(long)row * DIM + 4 * lane] = pd;
        *(float4*)&out_pu[(long)row * DIM + 4 * lane] = pu;
        float4 f;
        f.x = hu.x + pd.x; f.y = hu.y + pd.y; f.z = hu.z + pd.z; f.w = hu.w + pd.w;
        *(float4*)&g_feat[row * 256 + 4 * lane] = f;
    }
}

// ---------------- e_i_hat = p_v + (text - bt)@Wt.T + (vis - bv)@Wv.T ----------------
// 32 rows/block, 128 threads: warp = 8 rows, lane = 4 dims
__global__ void k_ei(const int* __restrict__ nodes_v,
                     const float* __restrict__ pre_text,
                     const float* __restrict__ pre_visual,
                     const float* __restrict__ item_prompt) {
    __shared__ float sA[32][64];
    __shared__ int s_item[32];
    int tid = threadIdx.x;
    int warp = tid >> 5, lane = tid & 31;
    int row0 = blockIdx.x * 32;

    if (tid < 32) s_item[tid] = nodes_v[row0 + tid];
    __syncthreads();

    float acc[8][4];
    #pragma unroll
    for (int r = 0; r < 8; ++r)
        #pragma unroll
        for (int j = 0; j < 4; ++j) acc[r][j] = 0.f;

    for (int c = 0; c < 18; ++c) {
        // load A chunk (32 rows x 64 k)
        for (int i = tid; i < 32 * 64; i += 128) {
            int r = i >> 6, kk = i & 63;
            long item = s_item[r];
            float v = (c < 6) ? pre_text[item * 384 + c * 64 + kk]
                              : pre_visual[item * 768 + (c - 6) * 64 + kk];
            sA[r][kk] = v;
        }
        __syncthreads();
        int kbase = c * 64;
        #pragma unroll 4
        for (int kk = 0; kk < 64; ++kk) {
            float4 w = *(const float4*)&g_Wc[(kbase + kk) * DIM + 4 * lane];
            #pragma unroll
            for (int r = 0; r < 8; ++r) {
                float a = sA[warp * 8 + r][kk];
                acc[r][0] = fmaf(a, w.x, acc[r][0]);
                acc[r][1] = fmaf(a, w.y, acc[r][1]);
                acc[r][2] = fmaf(a, w.z, acc[r][2]);
                acc[r][3] = fmaf(a, w.w, acc[r][3]);
            }
        }
        __syncthreads();
    }

    float4 cb = *(const float4*)&g_cbias[4 * lane];
    #pragma unroll
    for (int r = 0; r < 8; ++r) {
        int row = row0 + warp * 8 + r;
        long item = s_item[warp * 8 + r];
        float4 ip = *(const float4*)&item_prompt[item * DIM + 4 * lane];
        float4 o;
        o.x = acc[r][0] + ip.x - cb.x;
        o.y = acc[r][1] + ip.y - cb.y;
        o.z = acc[r][2] + ip.z - cb.z;
        o.w = acc[r][3] + ip.w - cb.w;
        *(float4*)&g_feat[row * 256 + 128 + 4 * lane] = o;
    }
}

// ---------------- f1 = relu(feat @ W1.T + b1) ----------------
__global__ void k_f1(const float* __restrict__ b1) {
    __shared__ float sA[32][64];
    int tid = threadIdx.x;
    int warp = tid >> 5, lane = tid & 31;
    int row0 = blockIdx.x * 32;

    float acc[8][4];
    #pragma unroll
    for (int r = 0; r < 8; ++r)
        #pragma unroll
        for (int j = 0; j < 4; ++j) acc[r][j] = 0.f;

    for (int c = 0; c < 4; ++c) {
        for (int i = tid; i < 32 * 64; i += 128) {
            int r = i >> 6, kk = i & 63;
            sA[r][kk] = g_feat[(row0 + r) * 256 + c * 64 + kk];
        }
        __syncthreads();
        int kbase = c * 64;
        #pragma unroll 4
        for (int kk = 0; kk < 64; ++kk) {
            float4 w = *(const float4*)&g_W1T[(kbase + kk) * DIM + 4 * lane];
            #pragma unroll
            for (int r = 0; r < 8; ++r) {
                float a = sA[warp * 8 + r][kk];
                acc[r][0] = fmaf(a, w.x, acc[r][0]);
                acc[r][1] = fmaf(a, w.y, acc[r][1]);
                acc[r][2] = fmaf(a, w.z, acc[r][2]);
                acc[r][3] = fmaf(a, w.w, acc[r][3]);
            }
        }
        __syncthreads();
    }
    float4 bb = *(const float4*)&b1[4 * lane];
    #pragma unroll
    for (int r = 0; r < 8; ++r) {
        int row = row0 + warp * 8 + r;
        float4 o;
        o.x = fmaxf(acc[r][0] + bb.x, 0.f);
        o.y = fmaxf(acc[r][1] + bb.y, 0.f);
        o.z = fmaxf(acc[r][2] + bb.z, 0.f);
        o.w = fmaxf(acc[r][3] + bb.w, 0.f);
        *(float4*)&g_f1[row * DIM + 4 * lane] = o;
    }
}

// ---------------- f1 batch stats, stage 1 (deterministic) ----------------
__global__ void k_stat1() {
    int tid = threadIdx.x;
    int b = blockIdx.x;
    float s = 0.f, q = 0.f;
    for (int r = 0; r < 64; ++r) {
        float x = g_f1[(b * 64 + r) * DIM + tid];
        s += x;
        q = fmaf(x, x, q);
    }
    g_p1s[b * 128 + tid] = s;
    g_p1q[b * 128 + tid] = q;
}

// ---------------- fold BN1 into W2 ----------------
__global__ void k_mid(const float* __restrict__ g1, const float* __restrict__ be1,
                      const float* __restrict__ W2, const float* __restrict__ b2) {
    __shared__ float sc[128], sh[128];
    int tid = threadIdx.x;
    float s = 0.f, q = 0.f;
    for (int i = 0; i < 64; ++i) {
        s += g_p1s[i * 128 + tid];
        q += g_p1q[i * 128 + tid];
    }
    float mean = s * (1.0f / (float)B_SZ);
    float var = q * (1.0f / (float)B_SZ) - mean * mean;
    float rstd = rsqrtf(var + 1e-5f);
    float scale = g1[tid] * rstd;
    sc[tid] = scale;
    sh[tid] = be1[tid] - mean * scale;
    __syncthreads();
    if (tid < 64) {
        int d = tid;
        float bacc = 0.f;
        for (int k = 0; k < 128; ++k) {
            float w = W2[d * 128 + k];
            g_effW2T[k * 64 + d] = w * sc[k];
            bacc = fmaf(w, sh[k], bacc);
        }
        g_effb2[d] = b2[d] + bacc;
    }
}

// ---------------- f2 = relu(f1 @ effW2T + effb2) ----------------
// 32 rows/block, 128 threads: warp = 8 rows, lane = 2 dims
__global__ void k_f2() {
    __shared__ float sA[32][64];
    int tid = threadIdx.x;
    int warp = tid >> 5, lane = tid & 31;
    int row0 = blockIdx.x * 32;

    float acc[8][2];
    #pragma unroll
    for (int r = 0; r < 8; ++r) { acc[r][0] = 0.f; acc[r][1] = 0.f; }

    for (int c = 0; c < 2; ++c) {
        for (int i = tid; i < 32 * 64; i += 128) {
            int r = i >> 6, kk = i & 63;
            sA[r][kk] = g_f1[(row0 + r) * DIM + c * 64 + kk];
        }
        __syncthreads();
        int kbase = c * 64;
        #pragma unroll 4
        for (int kk = 0; kk < 64; ++kk) {
            float2 w = *(const float2*)&g_effW2T[(kbase + kk) * 64 + 2 * lane];
            #pragma unroll
            for (int r = 0; r < 8; ++r) {
                float a = sA[warp * 8 + r][kk];
                acc[r][0] = fmaf(a, w.x, acc[r][0]);
                acc[r][1] = fmaf(a, w.y, acc[r][1]);
            }
        }
        __syncthreads();
    }
    float2 bb = *(const float2*)&g_effb2[2 * lane];
    #pragma unroll
    for (int r = 0; r < 8; ++r) {
        int row = row0 + warp * 8 + r;
        float2 o;
        o.x = fmaxf(acc[r][0] + bb.x, 0.f);
        o.y = fmaxf(acc[r][1] + bb.y, 0.f);
        *(float2*)&g_f2[row * 64 + 2 * lane] = o;
    }
}

// ---------------- f2 batch stats, stage 1 ----------------
__global__ void k_stat2() {
    int tid = threadIdx.x;  // 64
    int b = blockIdx.x;
    float s = 0.f, q = 0.f;
    for (int r = 0; r < 64; ++r) {
        float x = g_f2[(b * 64 + r) * 64 + tid];
        s += x;
        q = fmaf(x, x, q);
    }
    g_p2s[b * 64 + tid] = s;
    g_p2q[b * 64 + tid] = q;
}

// ---------------- fold BN2 into Wp ----------------
__global__ void k_mid2(const float* __restrict__ g2, const float* __restrict__ be2,
                       const float* __restrict__ Wp, const float* __restrict__ bp) {
    __shared__ float contrib[64];
    int tid = threadIdx.x;  // 64
    float s = 0.f, q = 0.f;
    for (int i = 0; i < 64; ++i) {
        s += g_p2s[i * 64 + tid];
        q += g_p2q[i * 64 + tid];
    }
    float mean = s * (1.0f / (float)B_SZ);
    float var = q * (1.0f / (float)B_SZ) - mean * mean;
    float rstd = rsqrtf(var + 1e-5f);
    float scale = g2[tid] * rstd;
    float shift = be2[tid] - mean * scale;
    float w = Wp[tid];
    g_effWp[tid] = w * scale;
    contrib[tid] = w * shift;
    __syncthreads();
    if (tid == 0) {
        float acc = bp[0];
        for (int i = 0; i < 64; ++i) acc += contrib[i];
        g_effbp = acc;
    }
}

// ---------------- pred = sigmoid(f2n @ Wp.T + bp) ----------------
__global__ void k_pred(float* __restrict__ out_pred) {
    int tid = threadIdx.x;
    int lane = tid & 31;
    int row = blockIdx.x * 8 + (tid >> 5);
    float a = g_f2[row * 64 + lane] * g_effWp[lane]
            + g_f2[row * 64 + 32 + lane] * g_effWp[32 + lane];
    #pragma unroll
    for (int o = 16; o > 0; o >>= 1) a += __shfl_down_sync(0xffffffffu, a, o);
    if (lane == 0) {
        float x = a + g_effbp;
        out_pred[row] = 1.0f / (1.0f + expf(-x));
    }
}

// ---------------- launcher ----------------
extern "C" void kernel_launch(void* const* d_in, const int* in_sizes, int n_in,
                              void* d_out, int out_size) {
    const int*   nodes_u       = (const int*)d_in[0];
    const int*   nodes_v       = (const int*)d_in[1];
    const int*   nodes_d       = (const int*)d_in[2];
    const int*   inter_items   = (const int*)d_in[3];
    const int*   top_n         = (const int*)d_in[4];
    const float* prototypes    = (const float*)d_in[5];
    const float* pre_text      = (const float*)d_in[6];
    const float* pre_visual    = (const float*)d_in[7];
    const float* Wt            = (const float*)d_in[8];
    const float* bt            = (const float*)d_in[9];
    const float* Wv            = (const float*)d_in[10];
    const float* bv            = (const float*)d_in[11];
    const float* user_prompt   = (const float*)d_in[12];
    const float* item_prompt   = (const float*)d_in[13];
    const float* domain_prompt = (const float*)d_in[14];
    const float* W1            = (const float*)d_in[15];
    const float* b1            = (const float*)d_in[16];
    const float* g1            = (const float*)d_in[17];
    const float* be1           = (const float*)d_in[18];
    const float* W2            = (const float*)d_in[19];
    const float* b2            = (const float*)d_in[20];
    const float* g2            = (const float*)d_in[21];
    const float* be2           = (const float*)d_in[22];
    const float* Wp            = (const float*)d_in[23];
    const float* bp            = (const float*)d_in[24];

    float* out      = (float*)d_out;
    float* out_pred = out;                         // [B]
    float* out_pu   = out + B_SZ;                  // [B, D]
    float* out_hu   = out + B_SZ + B_SZ * DIM;     // [B, D]
    float* out_pd   = out + B_SZ + 2 * B_SZ * DIM; // [B, D]

    k_transpose<<<704, 256>>>(Wt, Wv, W1);
    k_cbias<<<128, 128>>>(Wt, Wv, bt, bv);
    k_hu<<<B_SZ / 8, 128>>>(nodes_u, nodes_d, inter_items, top_n, prototypes,
                            user_prompt, domain_prompt, out_pu, out_hu, out_pd);
    k_ei<<<B_SZ / 32, 128>>>(nodes_v, pre_text, pre_visual, item_prompt);
    k_f1<<<B_SZ / 32, 128>>>(b1);
    k_stat1<<<64, 128>>>();
    k_mid<<<1, 128>>>(g1, be1, W2, b2);
    k_f2<<<B_SZ / 32, 128>>>();
    k_stat2<<<64, 64>>>();
    k_mid2<<<1, 64>>>(g2, be2, Wp, bp);
    k_pred<<<B_SZ / 8, 256>>>(out_pred);
}

// round 2
// speedup vs baseline: 1.0862x; 1.0862x over previous
#include <cuda_runtime.h>
#include <math.h>

#define B_SZ      4096
#define DIM       128
#define HIST      50
#define TOPN      4
#define PROTO     1024
#define ITEM_NUM  100000
#define KTOT      1152   // 384 text + 768 visual

typedef unsigned long long u64;

// ---------------- f32x2 helpers ----------------
__device__ __forceinline__ void ffma2(u64& d, u64 a, u64 b) {
    asm("fma.rn.f32x2 %0, %1, %2, %0;" : "+l"(d) : "l"(a), "l"(b));
}
__device__ __forceinline__ u64 pk2(float x) {
    u64 r; asm("mov.b64 %0, {%1, %1};" : "=l"(r) : "r"(__float_as_uint(x))); return r;
}
__device__ __forceinline__ float2 up2(u64 v) {
    float2 f; asm("mov.b64 {%0, %1}, %2;" : "=f"(f.x), "=f"(f.y) : "l"(v)); return f;
}

// ---------------- scratch ----------------
__device__ float g_Wc[KTOT * DIM];      // [k][d] combined (Wt|Wv)
__device__ float g_W1T[256 * DIM];      // [k][d]
__device__ float g_cbias[DIM];
__device__ float g_feat[B_SZ * 256];    // [h_u_hat | e_i_hat]
__device__ float g_f1[B_SZ * DIM];
__device__ float g_f2[B_SZ * 64];
__device__ float g_p1s[256 * 128];
__device__ float g_p1q[256 * 128];
__device__ float g_p2s[256 * 64];
__device__ float g_p2q[256 * 64];
__device__ float g_effW2T[128 * 64];
__device__ float g_effb2[64];
__device__ float g_effWp[64];
__device__ float g_effbp;

// ---------------- prep: transposes ----------------
__global__ void k_transpose(const float* __restrict__ Wt,
                            const float* __restrict__ Wv,
                            const float* __restrict__ W1) {
    int i = blockIdx.x * blockDim.x + threadIdx.x;
    const int T1 = KTOT * DIM;
    const int T2 = 256 * DIM;
    if (i < T1) {
        int k = i >> 7, d = i & 127;
        g_Wc[i] = (k < 384) ? Wt[d * 384 + k] : Wv[d * 768 + (k - 384)];
    } else if (i < T1 + T2) {
        int j = i - T1;
        int k = j >> 7, d = j & 127;
        g_W1T[j] = W1[d * 256 + k];
    }
}

// ---------------- prep: constant bias projection ----------------
__global__ void k_cbias(const float* __restrict__ Wt, const float* __restrict__ Wv,
                        const float* __restrict__ bt, const float* __restrict__ bv) {
    int d = blockIdx.x;
    int tid = threadIdx.x;
    float s = 0.f;
    for (int k = tid; k < KTOT; k += 128) {
        float w = (k < 384) ? Wt[d * 384 + k] : Wv[d * 768 + (k - 384)];
        float b = (k < 384) ? bt[k] : bv[k - 384];
        s = fmaf(w, b, s);
    }
    __shared__ float red[128];
    red[tid] = s;
    __syncthreads();
    for (int o = 64; o > 0; o >>= 1) {
        if (tid < o) red[tid] += red[tid + o];
        __syncthreads();
    }
    if (tid == 0) g_cbias[d] = red[0];
}

// ---------------- h_u + prompt gathers ----------------
// 16 rows/block, 256 threads (8 warps), warp = 2 rows, lane = 4 dims
__global__ void __launch_bounds__(256) k_hu(
                     const int* __restrict__ nodes_u, const int* __restrict__ nodes_d,
                     const int* __restrict__ inter_items, const int* __restrict__ top_n,
                     const float* __restrict__ proto,
                     const float* __restrict__ user_prompt,
                     const float* __restrict__ domain_prompt,
                     float* __restrict__ out_pu, float* __restrict__ out_hu,
                     float* __restrict__ out_pd) {
    __shared__ unsigned mask[16][32];                // bitmask per row
    __shared__ unsigned sfm[8][PROTO];               // packed pair mask (bf16-bit trick)
    __shared__ float s_invc[16];

    int tid = threadIdx.x;
    int warp = tid >> 5, lane = tid & 31;
    int row0 = blockIdx.x * 16;

    for (int i = tid; i < 16 * 32; i += 256) ((unsigned*)mask)[i] = 0u;
    __syncthreads();

    // 16 rows * 50 items * 2 views * 4 = 6400 insertions
    for (int t = tid; t < 6400; t += 256) {
        int r = t / 400;
        int e = t - r * 400;
        int slot = e >> 3;
        int w = e & 7;
        int half = w >> 2;
        int j = w & 3;
        int item = inter_items[(row0 + r) * HIST + slot];
        int p = top_n[(item + half * ITEM_NUM) * TOPN + j];
        atomicOr(&mask[r][p >> 5], 1u << (p & 31));
    }
    __syncthreads();

    // pack pair masks: low16 = hi-bits of float(m_even), high16 = hi-bits of float(m_odd)
    for (int i = tid; i < 8 * PROTO; i += 256) {
        int pr = i >> 10, p = i & (PROTO - 1);
        unsigned b0 = (mask[2 * pr][p >> 5] >> (p & 31)) & 1u;
        unsigned b1 = (mask[2 * pr + 1][p >> 5] >> (p & 31)) & 1u;
        sfm[pr][p] = (b0 ? 0x3F80u : 0u) | (b1 ? 0x3F800000u : 0u);
    }
    if (tid < 16) {
        int c = 0;
        #pragma unroll
        for (int w = 0; w < 32; ++w) c += __popc(mask[tid][w]);
        s_invc[tid] = 1.0f / (float)c;
    }
    __syncthreads();

    u64 a0a = 0, a0b = 0, a1a = 0, a1b = 0;
    const float* pbase = proto + 4 * lane;

    #pragma unroll 8
    for (int p = 0; p < PROTO; ++p) {
        ulonglong2 w2 = *(const ulonglong2*)(pbase + p * DIM);
        unsigned u = sfm[warp][p];
        u64 m0 = pk2(__uint_as_float(u << 16));
        u64 m1 = pk2(__uint_as_float(u & 0xFFFF0000u));
        ffma2(a0a, m0, w2.x); ffma2(a0b, m0, w2.y);
        ffma2(a1a, m1, w2.x); ffma2(a1b, m1, w2.y);
    }

    int r0 = 2 * warp;
    #pragma unroll
    for (int rr = 0; rr < 2; ++rr) {
        int r = r0 + rr;
        int row = row0 + r;
        float ic = s_invc[r];
        float2 fa = up2(rr == 0 ? a0a : a1a);
        float2 fb = up2(rr == 0 ? a0b : a1b);
        float4 hu;
        hu.x = fa.x * ic; hu.y = fa.y * ic; hu.z = fb.x * ic; hu.w = fb.y * ic;
        int dn = nodes_d[row];
        int un = nodes_u[row];
        float4 pd = *(const float4*)&domain_prompt[dn * DIM + 4 * lane];
        float4 pu = *(const float4*)&user_prompt[(long)un * DIM + 4 * lane];
        *(float4*)&out_hu[(long)row * DIM + 4 * lane] = hu;
        *(float4*)&out_pd[(long)row * DIM + 4 * lane] = pd;
        *(float4*)&out_pu[(long)row * DIM + 4 * lane] = pu;
        float4 f;
        f.x = hu.x + pd.x; f.y = hu.y + pd.y; f.z = hu.z + pd.z; f.w = hu.w + pd.w;
        *(float4*)&g_feat[row * 256 + 4 * lane] = f;
    }
}

// ---------------- e_i_hat ----------------
// 16 rows/block, 256 threads (8 warps), warp = 2 rows, lane = 4 dims
// K staged in 3 chunks of 384 floats/row (24 KB smem), register-prefetched.
__global__ void __launch_bounds__(256) k_ei(
                     const int* __restrict__ nodes_v,
                     const float* __restrict__ pre_text,
                     const float* __restrict__ pre_visual,
                     const float* __restrict__ item_prompt) {
    __shared__ float sA[16 * 384];
    __shared__ int s_item[16];
    int tid = threadIdx.x;
    int warp = tid >> 5, lane = tid & 31;
    int row0 = blockIdx.x * 16;

    if (tid < 16) s_item[tid] = nodes_v[row0 + tid];
    __syncthreads();

    u64 a0a = 0, a0b = 0, a1a = 0, a1b = 0;
    int r0 = 2 * warp;
    const float* sa0 = sA + r0 * 384;
    const float* sa1 = sA + (r0 + 1) * 384;

    float4 pre[6];
    // prefetch chunk 0 (text[0:384])
    #pragma unroll
    for (int j = 0; j < 6; ++j) {
        int f4 = tid + j * 256;
        int row = f4 / 96, col = f4 % 96;
        pre[j] = *(const float4*)&pre_text[(long)s_item[row] * 384 + col * 4];
    }

    for (int c = 0; c < 3; ++c) {
        __syncthreads();
        #pragma unroll
        for (int j = 0; j < 6; ++j) {
            int f4 = tid + j * 256;
            int row = f4 / 96, col = f4 % 96;
            *(float4*)&sA[row * 384 + col * 4] = pre[j];
        }
        __syncthreads();
        if (c < 2) {
            // prefetch next chunk: c=0 -> vis[0:384], c=1 -> vis[384:768]
            long off = (c == 0) ? 0 : 384;
            #pragma unroll
            for (int j = 0; j < 6; ++j) {
                int f4 = tid + j * 256;
                int row = f4 / 96, col = f4 % 96;
                pre[j] = *(const float4*)&pre_visual[(long)s_item[row] * 768 + off + col * 4];
            }
        }
        const float* wp = g_Wc + (long)c * 384 * DIM + 4 * lane;
        #pragma unroll 8
        for (int kk = 0; kk < 384; ++kk) {
            ulonglong2 w2 = *(const ulonglong2*)(wp + kk * DIM);
            u64 p0 = pk2(sa0[kk]);
            u64 p1 = pk2(sa1[kk]);
            ffma2(a0a, p0, w2.x); ffma2(a0b, p0, w2.y);
            ffma2(a1a, p1, w2.x); ffma2(a1b, p1, w2.y);
        }
    }

    float4 cb = *(const float4*)&g_cbias[4 * lane];
    #pragma unroll
    for (int rr = 0; rr < 2; ++rr) {
        int r = r0 + rr;
        int row = row0 + r;
        long item = s_item[r];
        float4 ip = *(const float4*)&item_prompt[item * DIM + 4 * lane];
        float2 fa = up2(rr == 0 ? a0a : a1a);
        float2 fb = up2(rr == 0 ? a0b : a1b);
        float4 o;
        o.x = fa.x + ip.x - cb.x;
        o.y = fa.y + ip.y - cb.y;
        o.z = fb.x + ip.z - cb.z;
        o.w = fb.y + ip.w - cb.w;
        *(float4*)&g_feat[row * 256 + 128 + 4 * lane] = o;
    }
}

// ---------------- f1 = relu(feat @ W1.T + b1), fused BN-stat partials ----------------
// 16 rows/block, 256 threads, warp = 2 rows, lane = 4 dims, K = 256
__global__ void __launch_bounds__(256) k_f1(const float* __restrict__ b1) {
    __shared__ float sA[16 * 256];
    __shared__ float s_out[16][128];
    int tid = threadIdx.x;
    int warp = tid >> 5, lane = tid & 31;
    int row0 = blockIdx.x * 16;

    #pragma unroll
    for (int j = 0; j < 4; ++j) {
        int f4 = tid + j * 256;            // 0..1023, row = f4/64, col4 = f4%64
        int row = f4 >> 6, col = f4 & 63;
        *(float4*)&sA[row * 256 + col * 4] =
            *(const float4*)&g_feat[(row0 + row) * 256 + col * 4];
    }
    __syncthreads();

    u64 a0a = 0, a0b = 0, a1a = 0, a1b = 0;
    int r0 = 2 * warp;
    const float* sa0 = sA + r0 * 256;
    const float* sa1 = sA + (r0 + 1) * 256;
    const float* wp = g_W1T + 4 * lane;

    #pragma unroll 8
    for (int kk = 0; kk < 256; ++kk) {
        ulonglong2 w2 = *(const ulonglong2*)(wp + kk * DIM);
        u64 p0 = pk2(sa0[kk]);
        u64 p1 = pk2(sa1[kk]);
        ffma2(a0a, p0, w2.x); ffma2(a0b, p0, w2.y);
        ffma2(a1a, p1, w2.x); ffma2(a1b, p1, w2.y);
    }

    float4 bb = *(const float4*)&b1[4 * lane];
    #pragma unroll
    for (int rr = 0; rr < 2; ++rr) {
        int r = r0 + rr;
        int row = row0 + r;
        float2 fa = up2(rr == 0 ? a0a : a1a);
        float2 fb = up2(rr == 0 ? a0b : a1b);
        float4 o;
        o.x = fmaxf(fa.x + bb.x, 0.f);
        o.y = fmaxf(fa.y + bb.y, 0.f);
        o.z = fmaxf(fb.x + bb.z, 0.f);
        o.w = fmaxf(fb.y + bb.w, 0.f);
        *(float4*)&g_f1[row * DIM + 4 * lane] = o;
        *(float4*)&s_out[r][4 * lane] = o;
    }
    __syncthreads();
    if (tid < 128) {
        float s = 0.f, q = 0.f;
        #pragma unroll
        for (int r = 0; r < 16; ++r) {
            float x = s_out[r][tid];
            s += x;
            q = fmaf(x, x, q);
        }
        g_p1s[blockIdx.x * 128 + tid] = s;
        g_p1q[blockIdx.x * 128 + tid] = q;
    }
}

// ---------------- fold BN1 into W2 ----------------
__global__ void k_mid(const float* __restrict__ g1, const float* __restrict__ be1,
                      const float* __restrict__ W2, const float* __restrict__ b2) {
    __shared__ float sc[128], sh[128];
    int tid = threadIdx.x;
    float s = 0.f, q = 0.f;
    for (int i = 0; i < 256; ++i) {
        s += g_p1s[i * 128 + tid];
        q += g_p1q[i * 128 + tid];
    }
    float mean = s * (1.0f / (float)B_SZ);
    float var = q * (1.0f / (float)B_SZ) - mean * mean;
    float rstd = rsqrtf(var + 1e-5f);
    float scale = g1[tid] * rstd;
    sc[tid] = scale;
    sh[tid] = be1[tid] - mean * scale;
    __syncthreads();
    if (tid < 64) {
        int d = tid;
        float bacc = 0.f;
        for (int k = 0; k < 128; ++k) {
            float w = W2[d * 128 + k];
            g_effW2T[k * 64 + d] = w * sc[k];
            bacc = fmaf(w, sh[k], bacc);
        }
        g_effb2[d] = b2[d] + bacc;
    }
}

// ---------------- f2 = relu(f1 @ effW2T + effb2), fused stat partials ----------------
// 16 rows/block, 256 threads, warp = 2 rows, lane = 2 dims, K = 128
__global__ void __launch_bounds__(256) k_f2() {
    __shared__ float sA[16 * 128];
    __shared__ float s_out[16][64];
    int tid = threadIdx.x;
    int warp = tid >> 5, lane = tid & 31;
    int row0 = blockIdx.x * 16;

    #pragma unroll
    for (int j = 0; j < 2; ++j) {
        int f4 = tid + j * 256;            // 0..511, row = f4/32, col4 = f4%32
        int row = f4 >> 5, col = f4 & 31;
        *(float4*)&sA[row * 128 + col * 4] =
            *(const float4*)&g_f1[(row0 + row) * DIM + col * 4];
    }
    __syncthreads();

    u64 a0 = 0, a1 = 0;
    int r0 = 2 * warp;
    const float* sa0 = sA + r0 * 128;
    const float* sa1 = sA + (r0 + 1) * 128;
    const float* wp = g_effW2T + 2 * lane;

    #pragma unroll 8
    for (int kk = 0; kk < 128; ++kk) {
        u64 w2 = *(const u64*)(wp + kk * 64);
        u64 p0 = pk2(sa0[kk]);
        u64 p1 = pk2(sa1[kk]);
        ffma2(a0, p0, w2);
        ffma2(a1, p1, w2);
    }

    float2 bb = *(const float2*)&g_effb2[2 * lane];
    #pragma unroll
    for (int rr = 0; rr < 2; ++rr) {
        int r = r0 + rr;
        int row = row0 + r;
        float2 fa = up2(rr == 0 ? a0 : a1);
        float2 o;
        o.x = fmaxf(fa.x + bb.x, 0.f);
        o.y = fmaxf(fa.y + bb.y, 0.f);
        *(float2*)&g_f2[row * 64 + 2 * lane] = o;
        *(float2*)&s_out[r][2 * lane] = o;
    }
    __syncthreads();
    if (tid < 64) {
        float s = 0.f, q = 0.f;
        #pragma unroll
        for (int r = 0; r < 16; ++r) {
            float x = s_out[r][tid];
            s += x;
            q = fmaf(x, x, q);
        }
        g_p2s[blockIdx.x * 64 + tid] = s;
        g_p2q[blockIdx.x * 64 + tid] = q;
    }
}

// ---------------- fold BN2 into Wp ----------------
__global__ void k_mid2(const float* __restrict__ g2, const float* __restrict__ be2,
                       const float* __restrict__ Wp, const float* __restrict__ bp) {
    __shared__ float contrib[64];
    int tid = threadIdx.x;  // 64
    float s = 0.f, q = 0.f;
    for (int i = 0; i < 256; ++i) {
        s += g_p2s[i * 64 + tid];
        q += g_p2q[i * 64 + tid];
    }
    float mean = s * (1.0f / (float)B_SZ);
    float var = q * (1.0f / (float)B_SZ) - mean * mean;
    float rstd = rsqrtf(var + 1e-5f);
    float scale = g2[tid] * rstd;
    float shift = be2[tid] - mean * scale;
    float w = Wp[tid];
    g_effWp[tid] = w * scale;
    contrib[tid] = w * shift;
    __syncthreads();
    if (tid == 0) {
        float acc = bp[0];
        for (int i = 0; i < 64; ++i) acc += contrib[i];
        g_effbp = acc;
    }
}

// ---------------- pred ----------------
__global__ void k_pred(float* __restrict__ out_pred) {
    int tid = threadIdx.x;
    int lane = tid & 31;
    int row = blockIdx.x * 8 + (tid >> 5);
    float a = g_f2[row * 64 + lane] * g_effWp[lane]
            + g_f2[row * 64 + 32 + lane] * g_effWp[32 + lane];
    #pragma unroll
    for (int o = 16; o > 0; o >>= 1) a += __shfl_down_sync(0xffffffffu, a, o);
    if (lane == 0) {
        float x = a + g_effbp;
        out_pred[row] = 1.0f / (1.0f + expf(-x));
    }
}

// ---------------- launcher ----------------
extern "C" void kernel_launch(void* const* d_in, const int* in_sizes, int n_in,
                              void* d_out, int out_size) {
    const int*   nodes_u       = (const int*)d_in[0];
    const int*   nodes_v       = (const int*)d_in[1];
    const int*   nodes_d       = (const int*)d_in[2];
    const int*   inter_items   = (const int*)d_in[3];
    const int*   top_n         = (const int*)d_in[4];
    const float* prototypes    = (const float*)d_in[5];
    const float* pre_text      = (const float*)d_in[6];
    const float* pre_visual    = (const float*)d_in[7];
    const float* Wt            = (const float*)d_in[8];
    const float* bt            = (const float*)d_in[9];
    const float* Wv            = (const float*)d_in[10];
    const float* bv            = (const float*)d_in[11];
    const float* user_prompt   = (const float*)d_in[12];
    const float* item_prompt   = (const float*)d_in[13];
    const float* domain_prompt = (const float*)d_in[14];
    const float* W1            = (const float*)d_in[15];
    const float* b1            = (const float*)d_in[16];
    const float* g1            = (const float*)d_in[17];
    const float* be1           = (const float*)d_in[18];
    const float* W2            = (const float*)d_in[19];
    const float* b2            = (const float*)d_in[20];
    const float* g2            = (const float*)d_in[21];
    const float* be2           = (const float*)d_in[22];
    const float* Wp            = (const float*)d_in[23];
    const float* bp            = (const float*)d_in[24];

    float* out      = (float*)d_out;
    float* out_pred = out;
    float* out_pu   = out + B_SZ;
    float* out_hu   = out + B_SZ + B_SZ * DIM;
    float* out_pd   = out + B_SZ + 2 * B_SZ * DIM;

    k_transpose<<<704, 256>>>(Wt, Wv, W1);
    k_cbias<<<128, 128>>>(Wt, Wv, bt, bv);
    k_hu<<<B_SZ / 16, 256>>>(nodes_u, nodes_d, inter_items, top_n, prototypes,
                             user_prompt, domain_prompt, out_pu, out_hu, out_pd);
    k_ei<<<B_SZ / 16, 256>>>(nodes_v, pre_text, pre_visual, item_prompt);
    k_f1<<<B_SZ / 16, 256>>>(b1);
    k_mid<<<1, 128>>>(g1, be1, W2, b2);
    k_f2<<<B_SZ / 16, 256>>>();
    k_mid2<<<1, 64>>>(g2, be2, Wp, bp);
    k_pred<<<B_SZ / 8, 256>>>(out_pred);
}

// round 3
// speedup vs baseline: 1.7656x; 1.6255x over previous
#include <cuda_runtime.h>
#include <math.h>

#define B_SZ      4096
#define DIM       128
#define HIST      50
#define TOPN      4
#define PROTO     1024
#define ITEM_NUM  100000
#define KTOT      1152   // 384 text + 768 visual
#define NPART     6      // K split into 6 parts of 192
#define KPART     192

typedef unsigned long long u64;

// ---------------- f32x2 helpers ----------------
__device__ __forceinline__ void ffma2(u64& d, u64 a, u64 b) {
    asm("fma.rn.f32x2 %0, %1, %2, %0;" : "+l"(d) : "l"(a), "l"(b));
}
__device__ __forceinline__ u64 pk2(float x) {
    u64 r; asm("mov.b64 %0, {%1, %1};" : "=l"(r) : "r"(__float_as_uint(x))); return r;
}
__device__ __forceinline__ float2 up2(u64 v) {
    float2 f; asm("mov.b64 {%0, %1}, %2;" : "=f"(f.x), "=f"(f.y) : "l"(v)); return f;
}

// ---------------- scratch ----------------
__device__ float g_Wc[KTOT * DIM];          // [k][d] combined (Wt|Wv)
__device__ float g_W1T[256 * DIM];          // [k][d]
__device__ float g_cbias[DIM];
__device__ float g_huf[B_SZ * DIM];         // h_u_hat = h_u + p_d
__device__ float g_part[NPART][B_SZ * DIM]; // e_i partial sums
__device__ float g_f1[B_SZ * DIM];
__device__ float g_f2[B_SZ * 64];
__device__ float g_p1s[256 * 128];
__device__ float g_p1q[256 * 128];
__device__ float g_p2s[256 * 64];
__device__ float g_p2q[256 * 64];
__device__ float g_effW2T[128 * 64];
__device__ float g_effb2[64];
__device__ float g_effWp[64];
__device__ float g_effbp;

// ---------------- prep: transposes + cbias (merged) ----------------
__global__ void k_prep(const float* __restrict__ Wt, const float* __restrict__ Wv,
                       const float* __restrict__ W1,
                       const float* __restrict__ bt, const float* __restrict__ bv) {
    int b = blockIdx.x;
    if (b < 576) {                      // g_Wc transpose: 147456 elements
        int i = b * 256 + threadIdx.x;
        int k = i >> 7, d = i & 127;
        g_Wc[i] = (k < 384) ? Wt[d * 384 + k] : Wv[d * 768 + (k - 384)];
    } else if (b < 704) {               // g_W1T transpose: 32768 elements
        int i = (b - 576) * 256 + threadIdx.x;
        int k = i >> 7, d = i & 127;
        g_W1T[i] = W1[d * 256 + k];
    } else {                            // cbias[d], d = b - 704
        int d = b - 704;
        int tid = threadIdx.x;
        float s = 0.f;
        for (int k = tid; k < KTOT; k += 256) {
            float w = (k < 384) ? Wt[d * 384 + k] : Wv[d * 768 + (k - 384)];
            float bb = (k < 384) ? bt[k] : bv[k - 384];
            s = fmaf(w, bb, s);
        }
        __shared__ float red[256];
        red[tid] = s;
        __syncthreads();
        for (int o = 128; o > 0; o >>= 1) {
            if (tid < o) red[tid] += red[tid + o];
            __syncthreads();
        }
        if (tid == 0) g_cbias[d] = red[0];
    }
}

// ---------------- h_u + prompt gathers ----------------
// 16 rows/block, 256 threads (8 warps), warp = 2 rows, lane = 4 dims
__global__ void __launch_bounds__(256) k_hu(
                     const int* __restrict__ nodes_u, const int* __restrict__ nodes_d,
                     const int* __restrict__ inter_items, const int* __restrict__ top_n,
                     const float* __restrict__ proto,
                     const float* __restrict__ user_prompt,
                     const float* __restrict__ domain_prompt,
                     float* __restrict__ out_pu, float* __restrict__ out_hu,
                     float* __restrict__ out_pd) {
    __shared__ unsigned mask[16][32];
    __shared__ unsigned sfm[8][PROTO];
    __shared__ float s_invc[16];

    int tid = threadIdx.x;
    int warp = tid >> 5, lane = tid & 31;
    int row0 = blockIdx.x * 16;

    for (int i = tid; i < 16 * 32; i += 256) ((unsigned*)mask)[i] = 0u;
    __syncthreads();

    for (int t = tid; t < 6400; t += 256) {
        int r = t / 400;
        int e = t - r * 400;
        int slot = e >> 3;
        int w = e & 7;
        int half = w >> 2;
        int j = w & 3;
        int item = inter_items[(row0 + r) * HIST + slot];
        int p = top_n[(item + half * ITEM_NUM) * TOPN + j];
        atomicOr(&mask[r][p >> 5], 1u << (p & 31));
    }
    __syncthreads();

    for (int i = tid; i < 8 * PROTO; i += 256) {
        int pr = i >> 10, p = i & (PROTO - 1);
        unsigned b0 = (mask[2 * pr][p >> 5] >> (p & 31)) & 1u;
        unsigned b1 = (mask[2 * pr + 1][p >> 5] >> (p & 31)) & 1u;
        sfm[pr][p] = (b0 ? 0x3F80u : 0u) | (b1 ? 0x3F800000u : 0u);
    }
    if (tid < 16) {
        int c = 0;
        #pragma unroll
        for (int w = 0; w < 32; ++w) c += __popc(mask[tid][w]);
        s_invc[tid] = 1.0f / (float)c;
    }
    __syncthreads();

    u64 a0a = 0, a0b = 0, a1a = 0, a1b = 0;
    const float* pbase = proto + 4 * lane;

    #pragma unroll 8
    for (int p = 0; p < PROTO; ++p) {
        ulonglong2 w2 = *(const ulonglong2*)(pbase + p * DIM);
        unsigned u = sfm[warp][p];
        u64 m0 = pk2(__uint_as_float(u << 16));
        u64 m1 = pk2(__uint_as_float(u & 0xFFFF0000u));
        ffma2(a0a, m0, w2.x); ffma2(a0b, m0, w2.y);
        ffma2(a1a, m1, w2.x); ffma2(a1b, m1, w2.y);
    }

    int r0 = 2 * warp;
    #pragma unroll
    for (int rr = 0; rr < 2; ++rr) {
        int r = r0 + rr;
        int row = row0 + r;
        float ic = s_invc[r];
        float2 fa = up2(rr == 0 ? a0a : a1a);
        float2 fb = up2(rr == 0 ? a0b : a1b);
        float4 hu;
        hu.x = fa.x * ic; hu.y = fa.y * ic; hu.z = fb.x * ic; hu.w = fb.y * ic;
        int dn = nodes_d[row];
        int un = nodes_u[row];
        float4 pd = *(const float4*)&domain_prompt[dn * DIM + 4 * lane];
        float4 pu = *(const float4*)&user_prompt[(long)un * DIM + 4 * lane];
        *(float4*)&out_hu[(long)row * DIM + 4 * lane] = hu;
        *(float4*)&out_pd[(long)row * DIM + 4 * lane] = pd;
        *(float4*)&out_pu[(long)row * DIM + 4 * lane] = pu;
        float4 f;
        f.x = hu.x + pd.x; f.y = hu.y + pd.y; f.z = hu.z + pd.z; f.w = hu.w + pd.w;
        *(float4*)&g_huf[row * DIM + 4 * lane] = f;
    }
}

// ---------------- e_i partial GEMM: split-K, grid (256, 6) ----------------
// 16 rows/block, K=192 per block, 256 threads, warp = 2 rows, lane = 4 dims
__global__ void __launch_bounds__(256) k_ei(
                     const int* __restrict__ nodes_v,
                     const float* __restrict__ pre_text,
                     const float* __restrict__ pre_visual,
                     const float* __restrict__ item_prompt) {
    __shared__ __align__(16) float dupA[16 * KPART * 2];   // 24 KB, (a,a) pairs
    __shared__ int s_item[16];

    int tid = threadIdx.x;
    int part = blockIdx.y;          // 0..5
    int row0 = blockIdx.x * 16;

    if (tid < 16) s_item[tid] = nodes_v[row0 + tid];
    __syncthreads();

    // stage 16x192 activation slice, duplicated: 3 float4 per thread
    #pragma unroll
    for (int j = 0; j < 3; ++j) {
        int f4 = tid + j * 256;          // 0..767
        int row = f4 / 48, c4 = f4 % 48; // 48 float4 per row
        long item = s_item[row];
        const float* src = (part < 2)
            ? &pre_text[item * 384 + part * KPART + c4 * 4]
            : &pre_visual[item * 768 + (part - 2) * KPART + c4 * 4];
        float4 v = *(const float4*)src;
        float* d = &dupA[(row * KPART + c4 * 4) * 2];
        ((float4*)d)[0] = make_float4(v.x, v.x, v.y, v.y);
        ((float4*)d)[1] = make_float4(v.z, v.z, v.w, v.w);
    }
    __syncthreads();

    int warp = tid >> 5, lane = tid & 31;
    int r0 = 2 * warp;
    const u64* sa0 = (const u64*)&dupA[r0 * KPART * 2];
    const u64* sa1 = (const u64*)&dupA[(r0 + 1) * KPART * 2];
    const float* wp = g_Wc + (long)part * KPART * DIM + 4 * lane;

    u64 a0a = 0, a0b = 0, a1a = 0, a1b = 0;
    #pragma unroll 8
    for (int kk = 0; kk < KPART; ++kk) {
        ulonglong2 w2 = *(const ulonglong2*)(wp + (long)kk * DIM);
        u64 p0 = sa0[kk];
        u64 p1 = sa1[kk];
        ffma2(a0a, p0, w2.x); ffma2(a0b, p0, w2.y);
        ffma2(a1a, p1, w2.x); ffma2(a1b, p1, w2.y);
    }

    #pragma unroll
    for (int rr = 0; rr < 2; ++rr) {
        int r = r0 + rr;
        int row = row0 + r;
        float2 fa = up2(rr == 0 ? a0a : a1a);
        float2 fb = up2(rr == 0 ? a0b : a1b);
        float4 o;
        o.x = fa.x; o.y = fa.y; o.z = fb.x; o.w = fb.y;
        if (part == 0) {  // fold item_prompt - cbias into partial 0
            long item = s_item[r];
            float4 ip = *(const float4*)&item_prompt[item * DIM + 4 * lane];
            float4 cb = *(const float4*)&g_cbias[4 * lane];
            o.x += ip.x - cb.x;
            o.y += ip.y - cb.y;
            o.z += ip.z - cb.z;
            o.w += ip.w - cb.w;
        }
        *(float4*)&g_part[part][row * DIM + 4 * lane] = o;
    }
}

// ---------------- f1 = relu(feat @ W1.T + b1), sums e_i partials in staging ----------------
// 16 rows/block, 256 threads, warp = 2 rows, lane = 4 dims, K = 256
__global__ void __launch_bounds__(256) k_f1(const float* __restrict__ b1) {
    __shared__ __align__(16) float dupA[16 * 256 * 2];   // 32 KB
    __shared__ float s_out[16][128];
    int tid = threadIdx.x;
    int warp = tid >> 5, lane = tid & 31;
    int row0 = blockIdx.x * 16;

    #pragma unroll
    for (int j = 0; j < 4; ++j) {
        int f4 = tid + j * 256;            // 0..1023
        int row = f4 >> 6, c4 = f4 & 63;   // 64 float4 per row
        float4 v;
        if (c4 < 32) {
            v = *(const float4*)&g_huf[(row0 + row) * DIM + c4 * 4];
        } else {
            int off = (row0 + row) * DIM + (c4 - 32) * 4;
            v = *(const float4*)&g_part[0][off];
            #pragma unroll
            for (int p = 1; p < NPART; ++p) {
                float4 t = *(const float4*)&g_part[p][off];
                v.x += t.x; v.y += t.y; v.z += t.z; v.w += t.w;
            }
        }
        float* d = &dupA[(row * 256 + c4 * 4) * 2];
        ((float4*)d)[0] = make_float4(v.x, v.x, v.y, v.y);
        ((float4*)d)[1] = make_float4(v.z, v.z, v.w, v.w);
    }
    __syncthreads();

    int r0 = 2 * warp;
    const u64* sa0 = (const u64*)&dupA[r0 * 256 * 2];
    const u64* sa1 = (const u64*)&dupA[(r0 + 1) * 256 * 2];
    const float* wp = g_W1T + 4 * lane;

    u64 a0a = 0, a0b = 0, a1a = 0, a1b = 0;
    #pragma unroll 8
    for (int kk = 0; kk < 256; ++kk) {
        ulonglong2 w2 = *(const ulonglong2*)(wp + (long)kk * DIM);
        u64 p0 = sa0[kk];
        u64 p1 = sa1[kk];
        ffma2(a0a, p0, w2.x); ffma2(a0b, p0, w2.y);
        ffma2(a1a, p1, w2.x); ffma2(a1b, p1, w2.y);
    }

    float4 bb = *(const float4*)&b1[4 * lane];
    #pragma unroll
    for (int rr = 0; rr < 2; ++rr) {
        int r = r0 + rr;
        int row = row0 + r;
        float2 fa = up2(rr == 0 ? a0a : a1a);
        float2 fb = up2(rr == 0 ? a0b : a1b);
        float4 o;
        o.x = fmaxf(fa.x + bb.x, 0.f);
        o.y = fmaxf(fa.y + bb.y, 0.f);
        o.z = fmaxf(fb.x + bb.z, 0.f);
        o.w = fmaxf(fb.y + bb.w, 0.f);
        *(float4*)&g_f1[row * DIM + 4 * lane] = o;
        *(float4*)&s_out[r][4 * lane] = o;
    }
    __syncthreads();
    if (tid < 128) {
        float s = 0.f, q = 0.f;
        #pragma unroll
        for (int r = 0; r < 16; ++r) {
            float x = s_out[r][tid];
            s += x;
            q = fmaf(x, x, q);
        }
        g_p1s[blockIdx.x * 128 + tid] = s;
        g_p1q[blockIdx.x * 128 + tid] = q;
    }
}

// ---------------- fold BN1 into W2 ----------------
__global__ void k_mid(const float* __restrict__ g1, const float* __restrict__ be1,
                      const float* __restrict__ W2, const float* __restrict__ b2) {
    __shared__ float sc[128], sh[128];
    int tid = threadIdx.x;
    float s = 0.f, q = 0.f;
    for (int i = 0; i < 256; ++i) {
        s += g_p1s[i * 128 + tid];
        q += g_p1q[i * 128 + tid];
    }
    float mean = s * (1.0f / (float)B_SZ);
    float var = q * (1.0f / (float)B_SZ) - mean * mean;
    float rstd = rsqrtf(var + 1e-5f);
    float scale = g1[tid] * rstd;
    sc[tid] = scale;
    sh[tid] = be1[tid] - mean * scale;
    __syncthreads();
    if (tid < 64) {
        int d = tid;
        float bacc = 0.f;
        for (int k = 0; k < 128; ++k) {
            float w = W2[d * 128 + k];
            g_effW2T[k * 64 + d] = w * sc[k];
            bacc = fmaf(w, sh[k], bacc);
        }
        g_effb2[d] = b2[d] + bacc;
    }
}

// ---------------- f2 = relu(f1 @ effW2T + effb2) ----------------
// 16 rows/block, 256 threads, warp = 2 rows, lane = 2 dims, K = 128
__global__ void __launch_bounds__(256) k_f2() {
    __shared__ __align__(16) float dupA[16 * 128 * 2];   // 16 KB
    __shared__ float s_out[16][64];
    int tid = threadIdx.x;
    int warp = tid >> 5, lane = tid & 31;
    int row0 = blockIdx.x * 16;

    #pragma unroll
    for (int j = 0; j < 2; ++j) {
        int f4 = tid + j * 256;            // 0..511
        int row = f4 >> 5, c4 = f4 & 31;
        float4 v = *(const float4*)&g_f1[(row0 + row) * DIM + c4 * 4];
        float* d = &dupA[(row * 128 + c4 * 4) * 2];
        ((float4*)d)[0] = make_float4(v.x, v.x, v.y, v.y);
        ((float4*)d)[1] = make_float4(v.z, v.z, v.w, v.w);
    }
    __syncthreads();

    int r0 = 2 * warp;
    const u64* sa0 = (const u64*)&dupA[r0 * 128 * 2];
    const u64* sa1 = (const u64*)&dupA[(r0 + 1) * 128 * 2];
    const float* wp = g_effW2T + 2 * lane;

    u64 a0 = 0, a1 = 0;
    #pragma unroll 8
    for (int kk = 0; kk < 128; ++kk) {
        u64 w2 = *(const u64*)(wp + kk * 64);
        u64 p0 = sa0[kk];
        u64 p1 = sa1[kk];
        ffma2(a0, p0, w2);
        ffma2(a1, p1, w2);
    }

    float2 bb = *(const float2*)&g_effb2[2 * lane];
    #pragma unroll
    for (int rr = 0; rr < 2; ++rr) {
        int r = r0 + rr;
        int row = row0 + r;
        float2 fa = up2(rr == 0 ? a0 : a1);
        float2 o;
        o.x = fmaxf(fa.x + bb.x, 0.f);
        o.y = fmaxf(fa.y + bb.y, 0.f);
        *(float2*)&g_f2[row * 64 + 2 * lane] = o;
        *(float2*)&s_out[r][2 * lane] = o;
    }
    __syncthreads();
    if (tid < 64) {
        float s = 0.f, q = 0.f;
        #pragma unroll
        for (int r = 0; r < 16; ++r) {
            float x = s_out[r][tid];
            s += x;
            q = fmaf(x, x, q);
        }
        g_p2s[blockIdx.x * 64 + tid] = s;
        g_p2q[blockIdx.x * 64 + tid] = q;
    }
}

// ---------------- fold BN2 into Wp ----------------
__global__ void k_mid2(const float* __restrict__ g2, const float* __restrict__ be2,
                       const float* __restrict__ Wp, const float* __restrict__ bp) {
    __shared__ float contrib[64];
    int tid = threadIdx.x;  // 64
    float s = 0.f, q = 0.f;
    for (int i = 0; i < 256; ++i) {
        s += g_p2s[i * 64 + tid];
        q += g_p2q[i * 64 + tid];
    }
    float mean = s * (1.0f / (float)B_SZ);
    float var = q * (1.0f / (float)B_SZ) - mean * mean;
    float rstd = rsqrtf(var + 1e-5f);
    float scale = g2[tid] * rstd;
    float shift = be2[tid] - mean * scale;
    float w = Wp[tid];
    g_effWp[tid] = w * scale;
    contrib[tid] = w * shift;
    __syncthreads();
    if (tid == 0) {
        float acc = bp[0];
        for (int i = 0; i < 64; ++i) acc += contrib[i];
        g_effbp = acc;
    }
}

// ---------------- pred ----------------
__global__ void k_pred(float* __restrict__ out_pred) {
    int tid = threadIdx.x;
    int lane = tid & 31;
    int row = blockIdx.x * 8 + (tid >> 5);
    float a = g_f2[row * 64 + lane] * g_effWp[lane]
            + g_f2[row * 64 + 32 + lane] * g_effWp[32 + lane];
    #pragma unroll
    for (int o = 16; o > 0; o >>= 1) a += __shfl_down_sync(0xffffffffu, a, o);
    if (lane == 0) {
        float x = a + g_effbp;
        out_pred[row] = 1.0f / (1.0f + expf(-x));
    }
}

// ---------------- launcher ----------------
extern "C" void kernel_launch(void* const* d_in, const int* in_sizes, int n_in,
                              void* d_out, int out_size) {
    const int*   nodes_u       = (const int*)d_in[0];
    const int*   nodes_v       = (const int*)d_in[1];
    const int*   nodes_d       = (const int*)d_in[2];
    const int*   inter_items   = (const int*)d_in[3];
    const int*   top_n         = (const int*)d_in[4];
    const float* prototypes    = (const float*)d_in[5];
    const float* pre_text      = (const float*)d_in[6];
    const float* pre_visual    = (const float*)d_in[7];
    const float* Wt            = (const float*)d_in[8];
    const float* bt            = (const float*)d_in[9];
    const float* Wv            = (const float*)d_in[10];
    const float* bv            = (const float*)d_in[11];
    const float* user_prompt   = (const float*)d_in[12];
    const float* item_prompt   = (const float*)d_in[13];
    const float* domain_prompt = (const float*)d_in[14];
    const float* W1            = (const float*)d_in[15];
    const float* b1            = (const float*)d_in[16];
    const float* g1            = (const float*)d_in[17];
    const float* be1           = (const float*)d_in[18];
    const float* W2            = (const float*)d_in[19];
    const float* b2            = (const float*)d_in[20];
    const float* g2            = (const float*)d_in[21];
    const float* be2           = (const float*)d_in[22];
    const float* Wp            = (const float*)d_in[23];
    const float* bp            = (const float*)d_in[24];

    float* out      = (float*)d_out;
    float* out_pred = out;
    float* out_pu   = out + B_SZ;
    float* out_hu   = out + B_SZ + B_SZ * DIM;
    float* out_pd   = out + B_SZ + 2 * B_SZ * DIM;

    k_prep<<<832, 256>>>(Wt, Wv, W1, bt, bv);
    k_hu<<<B_SZ / 16, 256>>>(nodes_u, nodes_d, inter_items, top_n, prototypes,
                             user_prompt, domain_prompt, out_pu, out_hu, out_pd);
    dim3 eg(B_SZ / 16, NPART);
    k_ei<<<eg, 256>>>(nodes_v, pre_text, pre_visual, item_prompt);
    k_f1<<<B_SZ / 16, 256>>>(b1);
    k_mid<<<1, 128>>>(g1, be1, W2, b2);
    k_f2<<<B_SZ / 16, 256>>>();
    k_mid2<<<1, 64>>>(g2, be2, Wp, bp);
    k_pred<<<B_SZ / 8, 256>>>(out_pred);
}